// round 15
// baseline (speedup 1.0000x reference)
#include <cuda_runtime.h>
#include <math.h>

#define NB 2
#define CC 64
#define NP 144
#define NT 2304
#define IH 96
#define IW 96
#define ID 32
#define VOLSZ (IH*IW*ID)
#define PS 160               // padded proto count (transposed layout [cc][PS])
#define NBLK 288
#define TPB 256

#define INV2SIG2 ((float)(1.0/(2.0*(128.0/2.355)*(128.0/2.355))))

// ---------------- scratch ----------------
__device__ float g_protosT[NB*CC*PS];   // [v][cc][PS]; pad p>=NP stays zero
__device__ float g_cp[NB*NP*3];
__device__ float g_temb [NB*NT*CC];
__device__ float g_tembn[NB*NT*CC];
__device__ float g_ct[NB*NT*3];
__device__ float g_s0e[NB*NT*CC];
__device__ float g_s0c[NB*NT*3];
__device__ float g_s1e[NB*NT*CC];
__device__ float g_s1c[NB*NT*3];
__device__ float g_tgt[NB*NT*NP];
__device__ float g_acc2[3*NB*NP*68];    // per-iter proto accumulators (atomic)
__device__ float g_acc[4];
__device__ unsigned g_flags[NBLK];
__device__ unsigned g_release;

// ---------------- flag-array grid barrier (monotonic, replay-safe) ----------------
__device__ __forceinline__ void grid_barrier(unsigned tgt){
    __syncthreads();
    if(blockIdx.x == 0){
        if(threadIdx.x == 0){
            __threadfence();
            *((volatile unsigned*)&g_flags[0]) = tgt;
        }
        for(int i = threadIdx.x; i < NBLK; i += TPB){
            while(*((volatile unsigned*)&g_flags[i]) < tgt){}
        }
        __threadfence();
        __syncthreads();
        if(threadIdx.x == 0){
            *((volatile unsigned*)&g_release) = tgt;
        }
    } else {
        if(threadIdx.x == 0){
            __threadfence();
            *((volatile unsigned*)&g_flags[blockIdx.x]) = tgt;
            while(*((volatile unsigned*)&g_release) < tgt){}
            __threadfence();
        }
        __syncthreads();
    }
}

// ---------------- helpers ----------------
__device__ __forceinline__ float unnorm_reflect(float c, float size){
    float x = ((c + 1.f)*size - 1.f)*0.5f;
    float xr = fabsf(x + 0.5f);
    float extra = fmodf(xr, size);
    float flips = floorf(xr / size);
    float r = (fmodf(flips, 2.f) == 0.f) ? extra : (size - extra);
    r -= 0.5f;
    return fminf(fmaxf(r, 0.f), size - 1.f);
}
__device__ __forceinline__ float warpMax(float x){
    #pragma unroll
    for(int o=16;o;o>>=1) x = fmaxf(x, __shfl_xor_sync(0xffffffffu, x, o));
    return x;
}
__device__ __forceinline__ float warpSum(float x){
    #pragma unroll
    for(int o=16;o;o>>=1) x += __shfl_xor_sync(0xffffffffu, x, o);
    return x;
}

__device__ __forceinline__ void trilerp_setup2(
    int x, int y, int z, int Dr, int Hr, int Wr,
    float tx, float ty, float tz,
    int xi[2], int yi[2], int zi[2], float wx[2], float wy[2], float wz[2],
    float* ux_o, float* uy_o, float* uz_o)
{
    float gx = ((float)x + 0.5f)*2.f/(float)Wr - 1.f + tx;
    float gy = ((float)y + 0.5f)*2.f/(float)Hr - 1.f + ty;
    float gz = ((float)z + 0.5f)*2.f/(float)Dr - 1.f + tz;
    float ux = unnorm_reflect(gx, (float)IW);
    float uy = unnorm_reflect(gy, (float)IH);
    float uz = unnorm_reflect(gz, (float)ID);
    float x0f = floorf(ux), y0f = floorf(uy), z0f = floorf(uz);
    float fx = ux-x0f, fy = uy-y0f, fz = uz-z0f;
    int x0=(int)x0f, y0=(int)y0f, z0=(int)z0f;
    xi[0]=min(max(x0,0),IW-1);  xi[1]=min(max(x0+1,0),IW-1);
    yi[0]=min(max(y0,0),IH-1);  yi[1]=min(max(y0+1,0),IH-1);
    zi[0]=min(max(z0,0),ID-1);  zi[1]=min(max(z0+1,0),ID-1);
    wx[0]=1.f-fx; wx[1]=fx; wy[0]=1.f-fy; wy[1]=fy; wz[0]=1.f-fz; wz[1]=fz;
    *ux_o=ux; *uy_o=uy; *uz_o=uz;
}

__device__ __forceinline__ float gather8(const float* __restrict__ base,
    const int xi[2], const int yi[2], const int zi[2],
    const float wx[2], const float wy[2], const float wz[2])
{
    float val = 0.f;
    #pragma unroll
    for(int dz=0; dz<2; dz++)
      #pragma unroll
      for(int dy=0; dy<2; dy++)
        #pragma unroll
        for(int dx=0; dx<2; dx++)
            val += wx[dx]*wy[dy]*wz[dz] *
                   base[((size_t)yi[dy]*IW + xi[dx])*ID + zi[dz]];
    return val;
}

// ---------------- coalesced sampling: grid (288, 4), 256 thr ----------------
struct SampleArgs {
    const float* emb[3]; const float* jit[3];
    float* outn[3]; float* outraw[3]; float* outc[3];
    const float* pemb; const float* pjit;
    float* poutT; float* pcoord;
};

__global__ void sample_all_kernel(SampleArgs a)
{
    __shared__ float tile[16*68];
    __shared__ float ssqw[8*16];
    __shared__ float invn[16];
    __shared__ float uzs[16];
    __shared__ float pssq[64];

    int s = blockIdx.y;
    int tid = threadIdx.x;

    if(s == 3){
        int v = blockIdx.x / NP;
        int n = blockIdx.x - v*NP;
        const int Dr=4, Hr=6, Wr=6;
        int z = n/(Hr*Wr); int rem = n - z*(Hr*Wr); int yy = rem/Wr; int xx = rem - yy*Wr;
        const float* jit = a.pjit;
        float tz = (jit[v*3+0]-0.5f)*2.f*(8.f/32.f);
        float ty = (jit[v*3+1]-0.5f)*2.f*(16.f/96.f);
        float tx = (jit[v*3+2]-0.5f)*2.f*(16.f/96.f);
        int xi[2],yi[2],zi[2]; float wx[2],wy[2],wz[2],ux,uy,uz;
        trilerp_setup2(xx,yy,z,Dr,Hr,Wr,tx,ty,tz,xi,yi,zi,wx,wy,wz,&ux,&uy,&uz);
        int c = tid;
        float val = 0.f;
        if(c < 64) val = gather8(a.pemb + (size_t)(v*CC+c)*VOLSZ, xi,yi,zi,wx,wy,wz);
        if(c < 64) pssq[c] = val*val;
        __syncthreads();
        if(c<32) pssq[c]+=pssq[c+32]; __syncthreads();
        if(c<16) pssq[c]+=pssq[c+16]; __syncthreads();
        if(c< 8) pssq[c]+=pssq[c+ 8]; __syncthreads();
        if(c< 4) pssq[c]+=pssq[c+ 4]; __syncthreads();
        if(c< 2) pssq[c]+=pssq[c+ 2]; __syncthreads();
        if(c< 1) pssq[c]+=pssq[c+ 1]; __syncthreads();
        float inv = 1.f / fmaxf(sqrtf(pssq[0]), 1e-8f);
        if(c < 64) a.poutT[(size_t)v*CC*PS + c*PS + n] = val*inv;
        if(c == 0){
            float* oc = a.pcoord + (size_t)(v*NP+n)*3;
            oc[0] = uy; oc[1] = ux; oc[2] = uz;
        }
        return;
    }

    int v  = blockIdx.x / 144;
    int yx = blockIdx.x - v*144;
    int yy = yx / 12, xx = yx - yy*12;
    const float* jit = a.jit[s];
    float tz = (jit[v*3+0]-0.5f)*2.f*(2.f/32.f);
    float ty = (jit[v*3+1]-0.5f)*2.f*(8.f/96.f);
    float tx = (jit[v*3+2]-0.5f)*2.f*(8.f/96.f);

    float gy = ((float)yy+0.5f)*(2.f/12.f) - 1.f + ty;
    float gx = ((float)xx+0.5f)*(2.f/12.f) - 1.f + tx;
    float uy = unnorm_reflect(gy, (float)IH);
    float ux = unnorm_reflect(gx, (float)IW);
    float y0f = floorf(uy), x0f = floorf(ux);
    float fy = uy-y0f, fx = ux-x0f;
    int y0 = (int)y0f, x0 = (int)x0f;
    int yi0 = min(max(y0,0),IH-1), yi1 = min(max(y0+1,0),IH-1);
    int xi0 = min(max(x0,0),IW-1), xi1 = min(max(x0+1,0),IW-1);
    int coff[4]; float wyx[4];
    coff[0]=(yi0*IW+xi0)*ID; wyx[0]=(1.f-fy)*(1.f-fx);
    coff[1]=(yi0*IW+xi1)*ID; wyx[1]=(1.f-fy)*fx;
    coff[2]=(yi1*IW+xi0)*ID; wyx[2]=fy*(1.f-fx);
    coff[3]=(yi1*IW+xi1)*ID; wyx[3]=fy*fx;

    int lane = tid & 31, warp = tid >> 5;
    int z = lane & 15;
    float gz = ((float)z+0.5f)*(2.f/16.f) - 1.f + tz;
    float uz = unnorm_reflect(gz, (float)ID);
    float z0f2 = floorf(uz); float fz = uz - z0f2; int zz0 = (int)z0f2;
    int zi0 = min(max(zz0,0),ID-1), zi1 = min(max(zz0+1,0),ID-1);
    float wz0 = 1.f-fz, wz1 = fz;
    if(tid < 16) uzs[tid] = uz;

    const float* emb = a.emb[s];
    size_t vbase = (size_t)v*CC*VOLSZ;

    float ssqacc = 0.f;
    #pragma unroll
    for(int pass=0; pass<8; pass++){
        int c = warp*8 + pass;
        const float* bc = emb + vbase + (size_t)c*VOLSZ;
        float r0 = bc[coff[0] + lane];
        float r1 = bc[coff[1] + lane];
        float r2 = bc[coff[2] + lane];
        float r3 = bc[coff[3] + lane];
        float v0 = wz0*__shfl_sync(0xffffffffu, r0, zi0) + wz1*__shfl_sync(0xffffffffu, r0, zi1);
        float v1 = wz0*__shfl_sync(0xffffffffu, r1, zi0) + wz1*__shfl_sync(0xffffffffu, r1, zi1);
        float v2 = wz0*__shfl_sync(0xffffffffu, r2, zi0) + wz1*__shfl_sync(0xffffffffu, r2, zi1);
        float v3 = wz0*__shfl_sync(0xffffffffu, r3, zi0) + wz1*__shfl_sync(0xffffffffu, r3, zi1);
        float val = wyx[0]*v0 + wyx[1]*v1 + wyx[2]*v2 + wyx[3]*v3;
        if(lane < 16){
            tile[z*68 + c] = val;
            ssqacc += val*val;
        }
    }
    if(lane < 16) ssqw[warp*16 + z] = ssqacc;
    __syncthreads();
    if(tid < 16){
        float ss = 0.f;
        #pragma unroll
        for(int w2=0; w2<8; w2++) ss += ssqw[w2*16+tid];
        invn[tid] = 1.f / fmaxf(sqrtf(ss), 1e-8f);
    }
    __syncthreads();

    int zo = tid >> 4, c4 = (tid & 15)*4;
    float4 tv = *(float4*)&tile[zo*68 + c4];
    int n = (zo*12 + yy)*12 + xx;
    size_t ob = ((size_t)v*NT + n)*64 + c4;
    float iv = invn[zo];
    float4 ov = make_float4(tv.x*iv, tv.y*iv, tv.z*iv, tv.w*iv);
    *(float4*)&a.outn[s][ob] = ov;
    if(a.outraw[s]) *(float4*)&a.outraw[s][ob] = tv;
    if(tid < 16){
        int n2 = (tid*12 + yy)*12 + xx;
        float* oc = a.outc[s] + ((size_t)v*NT + n2)*3;
        oc[0] = uy; oc[1] = ux; oc[2] = uzs[tid];
    }
}

// ================= fused EM + loss persistent kernel =================
// 288 blocks x 256 threads, 2 blocks/SM.

__device__ __forceinline__ void stage_protos(float* spT, const float* __restrict__ prT, int v){
    int tid = threadIdx.x;
    const float4* src = (const float4*)(prT + (size_t)v*CC*PS);
    float4* dst = (float4*)spT;
    #pragma unroll
    for(int k=0; k<CC*PS/4/TPB; k++)
        dst[tid + k*TPB] = src[tid + k*TPB];
}

__device__ __forceinline__ void dot2(const float* __restrict__ spT, int lane,
                                     const float r[2][2], float acc[2][5]){
    #pragma unroll
    for(int q=0;q<2;q++)
        #pragma unroll
        for(int j=0;j<5;j++) acc[q][j]=0.f;
    #pragma unroll
    for(int h=0;h<2;h++){
        #pragma unroll 8
        for(int cc2=0; cc2<32; cc2++){
            const float* row = spT + (h*32+cc2)*PS + lane;
            float p0=row[0], p1=row[32], p2=row[64], p3=row[96], p4=row[128];
            #pragma unroll
            for(int q=0;q<2;q++){
                float vv = __shfl_sync(0xffffffffu, r[h][q], cc2);
                acc[q][0]=fmaf(vv,p0,acc[q][0]);
                acc[q][1]=fmaf(vv,p1,acc[q][1]);
                acc[q][2]=fmaf(vv,p2,acc[q][2]);
                acc[q][3]=fmaf(vv,p3,acc[q][3]);
                acc[q][4]=fmaf(vv,p4,acc[q][4]);
            }
        }
    }
}

// fused assign + mini-update (EM iterations): w stays in smem; proto sums
// accumulate directly into g_acc2[it] via atomics.
__device__ __forceinline__ void assign_update_phase(
    float* dyn, const float* __restrict__ tn, const float* __restrict__ ct,
    const float* __restrict__ temb,
    const float* __restrict__ prT, const float* __restrict__ cp, int it)
{
    float* spT  = dyn;              // 64*PS = 10240
    float* scpx = spT + 64*PS;      // 160
    float* scpy = scpx + 160;
    float* scpz = scpy + 160;
    float* sw2  = scpz + 160;       // 16*148 = 2368
    float* st   = sw2 + 16*148;     // 16*64 = 1024
    float* sct  = st + 1024;        // 48

    int tid = threadIdx.x, lane = tid&31, wid = tid>>5;
    int v  = blockIdx.x / (NT/16);
    int n0 = (blockIdx.x - v*(NT/16))*16;

    stage_protos(spT, prT, v);
    for(int i=tid; i<160; i+=TPB){
        float x=0.f, yv=0.f, z=0.f;
        if(i<NP){ x=cp[(v*NP+i)*3+0]; yv=cp[(v*NP+i)*3+1]; z=cp[(v*NP+i)*3+2]; }
        scpx[i]=x; scpy[i]=yv; scpz[i]=z;
    }
    {
        const float4* src = (const float4*)(temb + ((size_t)v*NT + n0)*64);
        ((float4*)st)[tid] = src[tid];               // 16*64 floats
    }
    if(tid < 48) sct[tid] = ct[((size_t)v*NT + n0)*3 + tid];
    __syncthreads();

    // ---- assign: compute w for this block's 16 points -> sw2 ----
    size_t gnb = (size_t)v*NT + n0 + wid*2;
    float r[2][2];
    #pragma unroll
    for(int q=0;q<2;q++){
        r[0][q] = tn[(gnb+q)*64 + lane];
        r[1][q] = tn[(gnb+q)*64 + 32 + lane];
    }
    float acc[2][5];
    dot2(spT, lane, r, acc);

    bool v4 = lane < 16;
    #pragma unroll
    for(int q=0;q<2;q++){
        int nl = wid*2 + q;
        float px = sct[nl*3+0], py = sct[nl*3+1], pz = sct[nl*3+2];
        float lg[5], mx = -1e30f;
        #pragma unroll
        for(int j=0;j<5;j++){
            lg[j] = acc[q][j]*(1.f/0.015f);
            if(j<4 || v4) mx = fmaxf(mx, lg[j]);
        }
        mx = warpMax(mx);
        float e[5], sum = 0.f;
        #pragma unroll
        for(int j=0;j<5;j++){ e[j] = (j<4||v4) ? expf(lg[j]-mx) : 0.f; sum += e[j]; }
        sum = warpSum(sum);
        float invs = 1.f/sum;
        #pragma unroll
        for(int j=0;j<5;j++){
            if(j==4 && !v4) continue;
            int p = lane + 32*j;
            float dx = px-scpx[p];
            float dy = py-scpy[p];
            float dz = (pz-scpz[p])*2.f;
            float aa = e[j]*invs * expf(-(dx*dx+dy*dy+dz*dz)*INV2SIG2);
            sw2[nl*148 + p] = aa;
        }
    }
    __syncthreads();

    // ---- mini-update GEMM: warp = 9 proto pairs over K=16 points ----
    int cg = lane & 15, kh = lane >> 4;
    float* base = g_acc2 + ((size_t)(it*NB + v)*NP)*68;
    #pragma unroll
    for(int pp=0; pp<9; pp++){
        int p = wid*2 + pp*16;
        float4 A0 = make_float4(0.f,0.f,0.f,0.f);
        float4 A1 = make_float4(0.f,0.f,0.f,0.f);
        float d0=0.f, d1=0.f, c0a=0.f, c1a=0.f;
        #pragma unroll
        for(int i=0;i<8;i++){
            int n = kh*8 + i;
            float2 wv = *(const float2*)&sw2[n*148 + p];
            float4 tv = *(const float4*)&st[n*64 + cg*4];
            A0.x = fmaf(wv.x,tv.x,A0.x); A0.y = fmaf(wv.x,tv.y,A0.y);
            A0.z = fmaf(wv.x,tv.z,A0.z); A0.w = fmaf(wv.x,tv.w,A0.w);
            A1.x = fmaf(wv.y,tv.x,A1.x); A1.y = fmaf(wv.y,tv.y,A1.y);
            A1.z = fmaf(wv.y,tv.z,A1.z); A1.w = fmaf(wv.y,tv.w,A1.w);
            d0 += wv.x; d1 += wv.y;
            if(cg < 3){
                float cv = sct[n*3 + cg];
                c0a = fmaf(wv.x,cv,c0a); c1a = fmaf(wv.y,cv,c1a);
            }
        }
        A0.x += __shfl_xor_sync(0xffffffffu, A0.x, 16);
        A0.y += __shfl_xor_sync(0xffffffffu, A0.y, 16);
        A0.z += __shfl_xor_sync(0xffffffffu, A0.z, 16);
        A0.w += __shfl_xor_sync(0xffffffffu, A0.w, 16);
        A1.x += __shfl_xor_sync(0xffffffffu, A1.x, 16);
        A1.y += __shfl_xor_sync(0xffffffffu, A1.y, 16);
        A1.z += __shfl_xor_sync(0xffffffffu, A1.z, 16);
        A1.w += __shfl_xor_sync(0xffffffffu, A1.w, 16);
        d0  += __shfl_xor_sync(0xffffffffu, d0, 16);
        d1  += __shfl_xor_sync(0xffffffffu, d1, 16);
        c0a += __shfl_xor_sync(0xffffffffu, c0a, 16);
        c1a += __shfl_xor_sync(0xffffffffu, c1a, 16);
        if(kh == 0){
            float* r0 = base + (size_t)p*68;
            float* r1 = r0 + 68;
            atomicAdd(&r0[cg*4+0], A0.x); atomicAdd(&r0[cg*4+1], A0.y);
            atomicAdd(&r0[cg*4+2], A0.z); atomicAdd(&r0[cg*4+3], A0.w);
            atomicAdd(&r1[cg*4+0], A1.x); atomicAdd(&r1[cg*4+1], A1.y);
            atomicAdd(&r1[cg*4+2], A1.z); atomicAdd(&r1[cg*4+3], A1.w);
            if(cg == 0){ atomicAdd(&r0[64], d0); atomicAdd(&r1[64], d1); }
            if(cg < 3){ atomicAdd(&r0[65+cg], c0a); atomicAdd(&r1[65+cg], c1a); }
        }
    }
}

// targets assign: writes g_tgt; stages spT/scp for loss reuse
__device__ __forceinline__ void assign_phase(
    float* dyn, const float* __restrict__ tn, const float* __restrict__ ct,
    const float* __restrict__ prT, const float* __restrict__ cp,
    float* __restrict__ out)
{
    float* spT  = dyn;            // 64*PS
    float* scpx = spT + 64*PS;    // 160
    float* scpy = scpx + 160;
    float* scpz = scpy + 160;

    int tid = threadIdx.x, lane = tid&31, wid = tid>>5;
    int v  = blockIdx.x / (NT/16);
    int n0 = (blockIdx.x - v*(NT/16))*16;

    stage_protos(spT, prT, v);
    for(int i=tid; i<160; i+=TPB){
        float x=0.f, yv=0.f, z=0.f;
        if(i<NP){ x=cp[(v*NP+i)*3+0]; yv=cp[(v*NP+i)*3+1]; z=cp[(v*NP+i)*3+2]; }
        scpx[i]=x; scpy[i]=yv; scpz[i]=z;
    }
    __syncthreads();

    size_t gnb = (size_t)v*NT + n0 + wid*2;
    float r[2][2];
    #pragma unroll
    for(int q=0;q<2;q++){
        r[0][q] = tn[(gnb+q)*64 + lane];
        r[1][q] = tn[(gnb+q)*64 + 32 + lane];
    }
    float acc[2][5];
    dot2(spT, lane, r, acc);

    bool v4 = lane < 16;
    #pragma unroll
    for(int q=0;q<2;q++){
        float lg[5], mx = -1e30f;
        #pragma unroll
        for(int j=0;j<5;j++){
            lg[j] = acc[q][j]*(1.f/0.015f);
            if(j<4 || v4) mx = fmaxf(mx, lg[j]);
        }
        mx = warpMax(mx);
        float e[5], sum = 0.f;
        #pragma unroll
        for(int j=0;j<5;j++){ e[j] = (j<4||v4) ? expf(lg[j]-mx) : 0.f; sum += e[j]; }
        sum = warpSum(sum);
        float invs = 1.f/sum;
        #pragma unroll
        for(int j=0;j<5;j++){
            if(j==4 && !v4) continue;
            int p = lane + 32*j;
            out[(gnb+q)*NP + p] = e[j]*invs;
        }
    }
}

// normalize: one warp per (v,p); reads accumulated row
__device__ __forceinline__ void normalize_phase(
    float* __restrict__ prT, float* __restrict__ cp, int it)
{
    int b = blockIdx.x;
    int v = b / NP, p = b - v*NP;
    int tid = threadIdx.x, lane = tid & 31;
    if(tid < 32){
        const float* row = g_acc2 + ((size_t)(it*NB + v)*NP + p)*68;
        float s0 = row[lane];
        float s1 = row[32+lane];
        float dd = row[64];
        float ca = (lane<3) ? row[65+lane] : 0.f;
        float d = dd + 1e-8f;
        float q0 = s0/d, q1 = s1/d;
        float ss = warpSum(q0*q0 + q1*q1);
        float inv = 1.f / fmaxf(sqrtf(ss), 1e-8f);
        prT[(size_t)v*CC*PS + lane*PS + p]      = q0*inv;
        prT[(size_t)v*CC*PS + (lane+32)*PS + p] = q1*inv;
        if(lane<3) cp[(v*NP+p)*3 + lane] = ca/d;
    }
}

// loss reuses spT/scp* staged by the immediately-preceding targets assign
__device__ __forceinline__ void loss_phase(
    float* dyn, const float* __restrict__ jt,
    const float* __restrict__ se0, const float* __restrict__ sc0,
    const float* __restrict__ se1, const float* __restrict__ sc1,
    const float* __restrict__ tg)
{
    float* spT  = dyn;               // staged
    float* scpx = spT + 64*PS;       // staged
    float* scpy = scpx + 160;
    float* scpz = scpy + 160;
    float* taw  = scpz + 160;        // 12
    float* tah  = taw + 12;          // 12
    float* tad  = tah + 12;          // 16
    __shared__ float bacc[2];

    int tid = threadIdx.x, lane = tid&31, wid = tid>>5;
    int v  = blockIdx.x / (NT/16);
    int m0 = (blockIdx.x - v*(NT/16))*16;

    {
        float tzj = (jt[v*3+0]-0.5f)*2.f*(2.f/32.f);
        float tyj = (jt[v*3+1]-0.5f)*2.f*(8.f/96.f);
        float txj = (jt[v*3+2]-0.5f)*2.f*(8.f/96.f);
        if(tid < 16){
            float gz = ((float)tid + 0.5f)*2.f/16.f - 1.f + tzj;
            tad[tid] = unnorm_reflect(gz, (float)ID);
        }
        if(tid >= 32 && tid < 44){
            int i = tid - 32;
            float gy = ((float)i + 0.5f)*2.f/12.f - 1.f + tyj;
            tah[i] = unnorm_reflect(gy, (float)IH);
        }
        if(tid >= 64 && tid < 76){
            int i = tid - 64;
            float gx = ((float)i + 0.5f)*2.f/12.f - 1.f + txj;
            taw[i] = unnorm_reflect(gx, (float)IW);
        }
    }

    for(int sidx=0; sidx<2; sidx++){
        const float* se  = sidx ? se1 : se0;
        const float* scc = sidx ? sc1 : sc0;
        if(tid < 2) bacc[tid] = 0.f;
        __syncthreads();

        size_t gmb = (size_t)v*NT + m0 + wid*2;
        float r[2][2], s0[2], s1[2], s2[2];
        #pragma unroll
        for(int q=0;q<2;q++){
            r[0][q] = se[(gmb+q)*64 + lane];
            r[1][q] = se[(gmb+q)*64 + 32 + lane];
            s0[q] = scc[(gmb+q)*3+0]; s1[q] = scc[(gmb+q)*3+1]; s2[q] = scc[(gmb+q)*3+2];
        }

        float best[2]; int bi[2];
        #pragma unroll
        for(int q=0;q<2;q++){
            float mh = 1e30f; int ih = 0;
            #pragma unroll
            for(int i=0;i<12;i++){
                float d = s0[q]-tah[i]; float t = d*d;
                if(t < mh){ mh = t; ih = i; }
            }
            float mw = 1e30f; int iw2 = 0;
            #pragma unroll
            for(int i=0;i<12;i++){
                float d = s1[q]-taw[i]; float t = d*d;
                if(t < mw){ mw = t; iw2 = i; }
            }
            float md = 1e30f; int id2 = 0;
            #pragma unroll
            for(int i=0;i<16;i++){
                float d = (s2[q]-tad[i])*2.f; float t = d*d;
                if(t < md){ md = t; id2 = i; }
            }
            best[q] = mh + (mw + md);
            bi[q]   = (id2*12 + ih)*12 + iw2;
        }

        float acc[2][5];
        dot2(spT, lane, r, acc);

        bool v4 = lane < 16;
        #pragma unroll
        for(int q=0;q<2;q++){
            float lg[5], mx = -1e30f;
            #pragma unroll
            for(int j=0;j<5;j++){
                lg[j] = acc[q][j]*(1.f/0.03f);
                if(j<4 || v4) mx = fmaxf(mx, lg[j]);
            }
            mx = warpMax(mx);
            float sum = 0.f;
            #pragma unroll
            for(int j=0;j<5;j++) sum += (j<4||v4) ? expf(lg[j]-mx) : 0.f;
            sum = warpSum(sum);
            float lse = mx + logf(sum);

            const float* tgrow = tg + ((size_t)v*NT + bi[q])*NP;
            float ts = 0.f, ctr = 0.f;
            #pragma unroll
            for(int j=0;j<5;j++){
                if(j==4 && !v4) continue;
                int p = lane + 32*j;
                float dx = s0[q]-scpx[p];
                float dy = s1[q]-scpy[p];
                float dz = (s2[q]-scpz[p])*2.f;
                float pos = (expf(-(dx*dx+dy*dy+dz*dz)*INV2SIG2) >= 0.5f) ? 1.f : 0.f;
                float t = tgrow[p]*pos;
                ts  += t;
                ctr += t*(lg[j]-lse);
            }
            ts  = warpSum(ts);
            ctr = warpSum(ctr);
            if(lane==0 && sqrtf(best[q]) <= 3.0f){
                atomicAdd(&bacc[0], -ctr/(ts + 1e-8f));
                atomicAdd(&bacc[1], 1.f);
            }
        }
        __syncthreads();
        if(tid==0){
            atomicAdd(&g_acc[sidx*2+0], bacc[0]);
            atomicAdd(&g_acc[sidx*2+1], bacc[1]);
        }
        __syncthreads();
    }
}

__global__ void __launch_bounds__(TPB, 2)
fused_em_kernel(float* __restrict__ out, const float* __restrict__ jt)
{
    extern __shared__ float dyn[];
    __shared__ unsigned s_base;

    if(threadIdx.x == 0) s_base = *((volatile unsigned*)&g_flags[blockIdx.x]);
    if(blockIdx.x == 0 && threadIdx.x < 4) g_acc[threadIdx.x] = 0.f;
    // zero this block's slice of g_acc2 (288*204 = 58752 = 3*2*144*68)
    if(threadIdx.x < 204) g_acc2[blockIdx.x*204 + threadIdx.x] = 0.f;
    __syncthreads();
    unsigned base = s_base;
    unsigned k = 0;

    grid_barrier(base + ++k);   // acc2 zeroing visible chip-wide

    for(int it=0; it<3; it++){
        assign_update_phase(dyn, g_tembn, g_ct, g_temb, g_protosT, g_cp, it);
        grid_barrier(base + ++k);
        normalize_phase(g_protosT, g_cp, it);
        grid_barrier(base + ++k);
    }
    assign_phase(dyn, g_tembn, g_ct, g_protosT, g_cp, g_tgt);
    grid_barrier(base + ++k);
    loss_phase(dyn, jt, g_s0e, g_s0c, g_s1e, g_s1c, g_tgt);
    grid_barrier(base + ++k);

    if(blockIdx.x == 0 && threadIdx.x == 0){
        out[0] = 0.5f*( g_acc[0]/(g_acc[1] + 1e-8f) + g_acc[2]/(g_acc[3] + 1e-8f) );
    }
}

// ---------------- host launch ----------------
extern "C" void kernel_launch(void* const* d_in, const int* in_sizes, int n_in,
                              void* d_out, int out_size)
{
    const float* e0  = (const float*)d_in[0];
    const float* e1  = (const float*)d_in[1];
    const float* et  = (const float*)d_in[2];
    const float* jp  = (const float*)d_in[7];
    const float* j0  = (const float*)d_in[8];
    const float* j1  = (const float*)d_in[9];
    const float* jt  = (const float*)d_in[10];

    float *protosT,*cp,*temb,*tembn,*ct,*s0e,*s0c,*s1e,*s1c;
    cudaGetSymbolAddress((void**)&protosT, g_protosT);
    cudaGetSymbolAddress((void**)&cp,     g_cp);
    cudaGetSymbolAddress((void**)&temb,   g_temb);
    cudaGetSymbolAddress((void**)&tembn,  g_tembn);
    cudaGetSymbolAddress((void**)&ct,     g_ct);
    cudaGetSymbolAddress((void**)&s0e,    g_s0e);
    cudaGetSymbolAddress((void**)&s0c,    g_s0c);
    cudaGetSymbolAddress((void**)&s1e,    g_s1e);
    cudaGetSymbolAddress((void**)&s1c,    g_s1c);

    // dyn smem: fused phase = 64*PS + 3*160 + 16*148 + 16*64 + 48 = 14160 floats
    size_t fsm = (size_t)(64*PS + 3*160 + 16*148 + 16*64 + 48)*sizeof(float);
    cudaFuncSetAttribute(fused_em_kernel, cudaFuncAttributeMaxDynamicSharedMemorySize, (int)fsm);

    SampleArgs a;
    a.emb[0]=et;  a.emb[1]=e0;  a.emb[2]=e1;
    a.jit[0]=jt;  a.jit[1]=j0;  a.jit[2]=j1;
    a.outn[0]=tembn; a.outn[1]=s0e; a.outn[2]=s1e;
    a.outraw[0]=temb; a.outraw[1]=nullptr; a.outraw[2]=nullptr;
    a.outc[0]=ct; a.outc[1]=s0c; a.outc[2]=s1c;
    a.pemb=et; a.pjit=jp; a.poutT=protosT; a.pcoord=cp;
    sample_all_kernel<<<dim3(288, 4), 256>>>(a);

    fused_em_kernel<<<NBLK, TPB, fsm>>>((float*)d_out, jt);
}

// round 16
// speedup vs baseline: 1.4564x; 1.4564x over previous
#include <cuda_runtime.h>
#include <math.h>

#define NB 2
#define CC 64
#define NP 144
#define NT 2304
#define IH 96
#define IW 96
#define ID 32
#define VOLSZ (IH*IW*ID)
#define NCHUNK 16
#define NPER   (NT/NCHUNK)   // 144
#define PS 160               // padded proto count (transposed layout [cc][PS])
#define NBLK 288
#define TPB 256

#define INV2SIG2 ((float)(1.0/(2.0*(128.0/2.355)*(128.0/2.355))))

// ---------------- scratch ----------------
__device__ float g_protosT[NB*CC*PS];   // [v][cc][PS]; pad p>=NP stays zero
__device__ float g_cp[NB*NP*3];
__device__ float g_temb [NB*NT*CC];
__device__ float g_tembn[NB*NT*CC];
__device__ float g_ct[NB*NT*3];
__device__ float g_s0e[NB*NT*CC];
__device__ float g_s0c[NB*NT*3];
__device__ float g_s1e[NB*NT*CC];
__device__ float g_s1c[NB*NT*3];
__device__ float g_w  [NB*NT*NP];
__device__ float g_tgt[NB*NT*NP];
__device__ float g_part[NCHUNK*NB*NP*68];
__device__ float g_acc[4];
__device__ unsigned g_flags[NBLK];
__device__ unsigned g_release;

// ---------------- flag-array grid barrier (monotonic, replay-safe) ----------------
__device__ __forceinline__ void grid_barrier(unsigned tgt){
    __syncthreads();
    if(blockIdx.x == 0){
        if(threadIdx.x == 0){
            __threadfence();
            *((volatile unsigned*)&g_flags[0]) = tgt;
        }
        for(int i = threadIdx.x; i < NBLK; i += TPB){
            while(*((volatile unsigned*)&g_flags[i]) < tgt){}
        }
        __threadfence();
        __syncthreads();
        if(threadIdx.x == 0){
            *((volatile unsigned*)&g_release) = tgt;
        }
    } else {
        if(threadIdx.x == 0){
            __threadfence();
            *((volatile unsigned*)&g_flags[blockIdx.x]) = tgt;
            while(*((volatile unsigned*)&g_release) < tgt){}
            __threadfence();
        }
        __syncthreads();
    }
}

// ---------------- helpers ----------------
__device__ __forceinline__ float unnorm_reflect(float c, float size){
    float x = ((c + 1.f)*size - 1.f)*0.5f;
    float xr = fabsf(x + 0.5f);
    float extra = fmodf(xr, size);
    float flips = floorf(xr / size);
    float r = (fmodf(flips, 2.f) == 0.f) ? extra : (size - extra);
    r -= 0.5f;
    return fminf(fmaxf(r, 0.f), size - 1.f);
}
__device__ __forceinline__ float warpMax(float x){
    #pragma unroll
    for(int o=16;o;o>>=1) x = fmaxf(x, __shfl_xor_sync(0xffffffffu, x, o));
    return x;
}
__device__ __forceinline__ float warpSum(float x){
    #pragma unroll
    for(int o=16;o;o>>=1) x += __shfl_xor_sync(0xffffffffu, x, o);
    return x;
}

__device__ __forceinline__ void trilerp_setup2(
    int x, int y, int z, int Dr, int Hr, int Wr,
    float tx, float ty, float tz,
    int xi[2], int yi[2], int zi[2], float wx[2], float wy[2], float wz[2],
    float* ux_o, float* uy_o, float* uz_o)
{
    float gx = ((float)x + 0.5f)*2.f/(float)Wr - 1.f + tx;
    float gy = ((float)y + 0.5f)*2.f/(float)Hr - 1.f + ty;
    float gz = ((float)z + 0.5f)*2.f/(float)Dr - 1.f + tz;
    float ux = unnorm_reflect(gx, (float)IW);
    float uy = unnorm_reflect(gy, (float)IH);
    float uz = unnorm_reflect(gz, (float)ID);
    float x0f = floorf(ux), y0f = floorf(uy), z0f = floorf(uz);
    float fx = ux-x0f, fy = uy-y0f, fz = uz-z0f;
    int x0=(int)x0f, y0=(int)y0f, z0=(int)z0f;
    xi[0]=min(max(x0,0),IW-1);  xi[1]=min(max(x0+1,0),IW-1);
    yi[0]=min(max(y0,0),IH-1);  yi[1]=min(max(y0+1,0),IH-1);
    zi[0]=min(max(z0,0),ID-1);  zi[1]=min(max(z0+1,0),ID-1);
    wx[0]=1.f-fx; wx[1]=fx; wy[0]=1.f-fy; wy[1]=fy; wz[0]=1.f-fz; wz[1]=fz;
    *ux_o=ux; *uy_o=uy; *uz_o=uz;
}

__device__ __forceinline__ float gather8(const float* __restrict__ base,
    const int xi[2], const int yi[2], const int zi[2],
    const float wx[2], const float wy[2], const float wz[2])
{
    float val = 0.f;
    #pragma unroll
    for(int dz=0; dz<2; dz++)
      #pragma unroll
      for(int dy=0; dy<2; dy++)
        #pragma unroll
        for(int dx=0; dx<2; dx++)
            val += wx[dx]*wy[dy]*wz[dz] *
                   base[((size_t)yi[dy]*IW + xi[dx])*ID + zi[dz]];
    return val;
}

// ---------------- coalesced sampling: grid (288, 4), 256 thr ----------------
struct SampleArgs {
    const float* emb[3]; const float* jit[3];
    float* outn[3]; float* outraw[3]; float* outc[3];
    const float* pemb; const float* pjit;
    float* poutT; float* pcoord;
};

__global__ void sample_all_kernel(SampleArgs a)
{
    __shared__ float tile[16*68];
    __shared__ float ssqw[8*16];
    __shared__ float invn[16];
    __shared__ float uzs[16];
    __shared__ float pssq[64];

    int s = blockIdx.y;
    int tid = threadIdx.x;

    if(s == 3){
        int v = blockIdx.x / NP;
        int n = blockIdx.x - v*NP;
        const int Dr=4, Hr=6, Wr=6;
        int z = n/(Hr*Wr); int rem = n - z*(Hr*Wr); int yy = rem/Wr; int xx = rem - yy*Wr;
        const float* jit = a.pjit;
        float tz = (jit[v*3+0]-0.5f)*2.f*(8.f/32.f);
        float ty = (jit[v*3+1]-0.5f)*2.f*(16.f/96.f);
        float tx = (jit[v*3+2]-0.5f)*2.f*(16.f/96.f);
        int xi[2],yi[2],zi[2]; float wx[2],wy[2],wz[2],ux,uy,uz;
        trilerp_setup2(xx,yy,z,Dr,Hr,Wr,tx,ty,tz,xi,yi,zi,wx,wy,wz,&ux,&uy,&uz);
        int c = tid;
        float val = 0.f;
        if(c < 64) val = gather8(a.pemb + (size_t)(v*CC+c)*VOLSZ, xi,yi,zi,wx,wy,wz);
        if(c < 64) pssq[c] = val*val;
        __syncthreads();
        if(c<32) pssq[c]+=pssq[c+32]; __syncthreads();
        if(c<16) pssq[c]+=pssq[c+16]; __syncthreads();
        if(c< 8) pssq[c]+=pssq[c+ 8]; __syncthreads();
        if(c< 4) pssq[c]+=pssq[c+ 4]; __syncthreads();
        if(c< 2) pssq[c]+=pssq[c+ 2]; __syncthreads();
        if(c< 1) pssq[c]+=pssq[c+ 1]; __syncthreads();
        float inv = 1.f / fmaxf(sqrtf(pssq[0]), 1e-8f);
        if(c < 64) a.poutT[(size_t)v*CC*PS + c*PS + n] = val*inv;
        if(c == 0){
            float* oc = a.pcoord + (size_t)(v*NP+n)*3;
            oc[0] = uy; oc[1] = ux; oc[2] = uz;
        }
        return;
    }

    int v  = blockIdx.x / 144;
    int yx = blockIdx.x - v*144;
    int yy = yx / 12, xx = yx - yy*12;
    const float* jit = a.jit[s];
    float tz = (jit[v*3+0]-0.5f)*2.f*(2.f/32.f);
    float ty = (jit[v*3+1]-0.5f)*2.f*(8.f/96.f);
    float tx = (jit[v*3+2]-0.5f)*2.f*(8.f/96.f);

    float gy = ((float)yy+0.5f)*(2.f/12.f) - 1.f + ty;
    float gx = ((float)xx+0.5f)*(2.f/12.f) - 1.f + tx;
    float uy = unnorm_reflect(gy, (float)IH);
    float ux = unnorm_reflect(gx, (float)IW);
    float y0f = floorf(uy), x0f = floorf(ux);
    float fy = uy-y0f, fx = ux-x0f;
    int y0 = (int)y0f, x0 = (int)x0f;
    int yi0 = min(max(y0,0),IH-1), yi1 = min(max(y0+1,0),IH-1);
    int xi0 = min(max(x0,0),IW-1), xi1 = min(max(x0+1,0),IW-1);
    int coff[4]; float wyx[4];
    coff[0]=(yi0*IW+xi0)*ID; wyx[0]=(1.f-fy)*(1.f-fx);
    coff[1]=(yi0*IW+xi1)*ID; wyx[1]=(1.f-fy)*fx;
    coff[2]=(yi1*IW+xi0)*ID; wyx[2]=fy*(1.f-fx);
    coff[3]=(yi1*IW+xi1)*ID; wyx[3]=fy*fx;

    int lane = tid & 31, warp = tid >> 5;
    int z = lane & 15;
    float gz = ((float)z+0.5f)*(2.f/16.f) - 1.f + tz;
    float uz = unnorm_reflect(gz, (float)ID);
    float z0f2 = floorf(uz); float fz = uz - z0f2; int zz0 = (int)z0f2;
    int zi0 = min(max(zz0,0),ID-1), zi1 = min(max(zz0+1,0),ID-1);
    float wz0 = 1.f-fz, wz1 = fz;
    if(tid < 16) uzs[tid] = uz;

    const float* emb = a.emb[s];
    size_t vbase = (size_t)v*CC*VOLSZ;

    float ssqacc = 0.f;
    #pragma unroll
    for(int pass=0; pass<8; pass++){
        int c = warp*8 + pass;
        const float* bc = emb + vbase + (size_t)c*VOLSZ;
        float r0 = bc[coff[0] + lane];
        float r1 = bc[coff[1] + lane];
        float r2 = bc[coff[2] + lane];
        float r3 = bc[coff[3] + lane];
        float v0 = wz0*__shfl_sync(0xffffffffu, r0, zi0) + wz1*__shfl_sync(0xffffffffu, r0, zi1);
        float v1 = wz0*__shfl_sync(0xffffffffu, r1, zi0) + wz1*__shfl_sync(0xffffffffu, r1, zi1);
        float v2 = wz0*__shfl_sync(0xffffffffu, r2, zi0) + wz1*__shfl_sync(0xffffffffu, r2, zi1);
        float v3 = wz0*__shfl_sync(0xffffffffu, r3, zi0) + wz1*__shfl_sync(0xffffffffu, r3, zi1);
        float val = wyx[0]*v0 + wyx[1]*v1 + wyx[2]*v2 + wyx[3]*v3;
        if(lane < 16){
            tile[z*68 + c] = val;
            ssqacc += val*val;
        }
    }
    if(lane < 16) ssqw[warp*16 + z] = ssqacc;
    __syncthreads();
    if(tid < 16){
        float ss = 0.f;
        #pragma unroll
        for(int w2=0; w2<8; w2++) ss += ssqw[w2*16+tid];
        invn[tid] = 1.f / fmaxf(sqrtf(ss), 1e-8f);
    }
    __syncthreads();

    int zo = tid >> 4, c4 = (tid & 15)*4;
    float4 tv = *(float4*)&tile[zo*68 + c4];
    int n = (zo*12 + yy)*12 + xx;
    size_t ob = ((size_t)v*NT + n)*64 + c4;
    float iv = invn[zo];
    float4 ov = make_float4(tv.x*iv, tv.y*iv, tv.z*iv, tv.w*iv);
    *(float4*)&a.outn[s][ob] = ov;
    if(a.outraw[s]) *(float4*)&a.outraw[s][ob] = tv;
    if(tid < 16){
        int n2 = (tid*12 + yy)*12 + xx;
        float* oc = a.outc[s] + ((size_t)v*NT + n2)*3;
        oc[0] = uy; oc[1] = ux; oc[2] = uzs[tid];
    }
}

// ================= fused EM + loss persistent kernel =================
// 288 blocks x 256 threads, 2 blocks/SM.

__device__ __forceinline__ void stage_protos(float* spT, const float* __restrict__ prT, int v){
    int tid = threadIdx.x;
    const float4* src = (const float4*)(prT + (size_t)v*CC*PS);
    float4* dst = (float4*)spT;
    #pragma unroll
    for(int k=0; k<CC*PS/4/TPB; k++)
        dst[tid + k*TPB] = src[tid + k*TPB];
}

__device__ __forceinline__ void dot2(const float* __restrict__ spT, int lane,
                                     const float r[2][2], float acc[2][5]){
    #pragma unroll
    for(int q=0;q<2;q++)
        #pragma unroll
        for(int j=0;j<5;j++) acc[q][j]=0.f;
    #pragma unroll
    for(int h=0;h<2;h++){
        #pragma unroll 8
        for(int cc2=0; cc2<32; cc2++){
            const float* row = spT + (h*32+cc2)*PS + lane;
            float p0=row[0], p1=row[32], p2=row[64], p3=row[96], p4=row[128];
            #pragma unroll
            for(int q=0;q<2;q++){
                float vv = __shfl_sync(0xffffffffu, r[h][q], cc2);
                acc[q][0]=fmaf(vv,p0,acc[q][0]);
                acc[q][1]=fmaf(vv,p1,acc[q][1]);
                acc[q][2]=fmaf(vv,p2,acc[q][2]);
                acc[q][3]=fmaf(vv,p3,acc[q][3]);
                acc[q][4]=fmaf(vv,p4,acc[q][4]);
            }
        }
    }
}

__device__ __forceinline__ void assign_phase(
    float* dyn, const float* __restrict__ tn, const float* __restrict__ ct,
    const float* __restrict__ prT, const float* __restrict__ cp,
    float* __restrict__ out, int useGauss)
{
    float* spT  = dyn;            // 64*PS
    float* scpx = spT + 64*PS;    // 160
    float* scpy = scpx + 160;
    float* scpz = scpy + 160;

    int tid = threadIdx.x, lane = tid&31, wid = tid>>5;
    int v  = blockIdx.x / (NT/16);
    int n0 = (blockIdx.x - v*(NT/16))*16;

    stage_protos(spT, prT, v);
    for(int i=tid; i<160; i+=TPB){
        float x=0.f, yv=0.f, z=0.f;
        if(i<NP){ x=cp[(v*NP+i)*3+0]; yv=cp[(v*NP+i)*3+1]; z=cp[(v*NP+i)*3+2]; }
        scpx[i]=x; scpy[i]=yv; scpz[i]=z;
    }
    __syncthreads();

    size_t gnb = (size_t)v*NT + n0 + wid*2;
    float r[2][2], px[2], py[2], pz[2];
    #pragma unroll
    for(int q=0;q<2;q++){
        r[0][q] = tn[(gnb+q)*64 + lane];
        r[1][q] = tn[(gnb+q)*64 + 32 + lane];
        px[q] = ct[(gnb+q)*3+0]; py[q] = ct[(gnb+q)*3+1]; pz[q] = ct[(gnb+q)*3+2];
    }

    float acc[2][5];
    dot2(spT, lane, r, acc);

    bool v4 = lane < 16;
    #pragma unroll
    for(int q=0;q<2;q++){
        float lg[5], mx = -1e30f;
        #pragma unroll
        for(int j=0;j<5;j++){
            lg[j] = acc[q][j]*(1.f/0.015f);
            if(j<4 || v4) mx = fmaxf(mx, lg[j]);
        }
        mx = warpMax(mx);
        float e[5], sum = 0.f;
        #pragma unroll
        for(int j=0;j<5;j++){ e[j] = (j<4||v4) ? expf(lg[j]-mx) : 0.f; sum += e[j]; }
        sum = warpSum(sum);
        float invs = 1.f/sum;
        #pragma unroll
        for(int j=0;j<5;j++){
            if(j==4 && !v4) continue;
            int p = lane + 32*j;
            float aa = e[j]*invs;
            if(useGauss){
                float dx = px[q]-scpx[p];
                float dy = py[q]-scpy[p];
                float dz = (pz[q]-scpz[p])*2.f;
                aa *= expf(-(dx*dx+dy*dy+dz*dz)*INV2SIG2);
            }
            out[(gnb+q)*NP + p] = aa;
        }
    }
}

// register-tiled update GEMM: warp = 2 protos; lane = (khalf, chan-group);
// thread tile = 2 protos x 4 channels over K=72 points; shfl folds K-halves.
__device__ __forceinline__ void update_phase(
    float* dyn, const float* __restrict__ w, const float* __restrict__ temb,
    const float* __restrict__ ct, float* __restrict__ part)
{
    float* sw_ = dyn;             // NPER*16
    float* st  = sw_ + NPER*16;   // NPER*64
    float* sc  = st + NPER*64;    // NPER*3

    int tid = threadIdx.x, lane = tid&31, wp = tid>>5;
    int cg = lane & 15;           // channel group (4 ch)
    int kh = lane >> 4;           // K half
    int bx = blockIdx.x;
    int v  = bx / (9*NCHUNK);
    int rr = bx - v*(9*NCHUNK);
    int ch = rr / 9, pblk = rr - ch*9;
    int p0b = pblk*16;
    size_t gn0 = (size_t)v*NT + ch*NPER;

    // vectorized w tile staging: 16 floats per n, 16B-aligned (NP*4=576B rows, p0b mult of 16)
    for(int i4 = tid; i4 < NPER*4; i4 += TPB){
        int n = i4 >> 2, j = i4 & 3;
        ((float4*)sw_)[i4] = *(const float4*)&w[(gn0+n)*NP + p0b + j*4];
    }
    {
        const float4* src = (const float4*)(temb + gn0*64);
        float4* dst = (float4*)st;
        for(int i=tid; i<NPER*16; i+=TPB) dst[i] = src[i];
    }
    for(int i=tid; i<NPER*3; i+=TPB) sc[i] = ct[gn0*3 + i];
    __syncthreads();

    float4 A0 = make_float4(0.f,0.f,0.f,0.f);
    float4 A1 = make_float4(0.f,0.f,0.f,0.f);
    float d0=0.f, d1=0.f, c0a=0.f, c1a=0.f;
    int nbeg = kh*(NPER/2);
    #pragma unroll 4
    for(int i=0; i<NPER/2; i++){
        int n = nbeg + i;
        float2 wv = *(const float2*)&sw_[n*16 + wp*2];
        float4 tv = *(const float4*)&st[n*64 + cg*4];
        A0.x = fmaf(wv.x,tv.x,A0.x); A0.y = fmaf(wv.x,tv.y,A0.y);
        A0.z = fmaf(wv.x,tv.z,A0.z); A0.w = fmaf(wv.x,tv.w,A0.w);
        A1.x = fmaf(wv.y,tv.x,A1.x); A1.y = fmaf(wv.y,tv.y,A1.y);
        A1.z = fmaf(wv.y,tv.z,A1.z); A1.w = fmaf(wv.y,tv.w,A1.w);
        d0 += wv.x; d1 += wv.y;
        if(cg < 3){
            float cv = sc[n*3 + cg];
            c0a = fmaf(wv.x,cv,c0a); c1a = fmaf(wv.y,cv,c1a);
        }
    }
    // fold K-halves (partner lane = lane^16)
    A0.x += __shfl_xor_sync(0xffffffffu, A0.x, 16);
    A0.y += __shfl_xor_sync(0xffffffffu, A0.y, 16);
    A0.z += __shfl_xor_sync(0xffffffffu, A0.z, 16);
    A0.w += __shfl_xor_sync(0xffffffffu, A0.w, 16);
    A1.x += __shfl_xor_sync(0xffffffffu, A1.x, 16);
    A1.y += __shfl_xor_sync(0xffffffffu, A1.y, 16);
    A1.z += __shfl_xor_sync(0xffffffffu, A1.z, 16);
    A1.w += __shfl_xor_sync(0xffffffffu, A1.w, 16);
    d0  += __shfl_xor_sync(0xffffffffu, d0, 16);
    d1  += __shfl_xor_sync(0xffffffffu, d1, 16);
    c0a += __shfl_xor_sync(0xffffffffu, c0a, 16);
    c1a += __shfl_xor_sync(0xffffffffu, c1a, 16);

    if(kh == 0){
        int p = p0b + wp*2;
        size_t b0 = ((size_t)(ch*NB + v)*NP + p)*68;
        size_t b1 = b0 + 68;
        *(float4*)&part[b0 + cg*4] = A0;
        *(float4*)&part[b1 + cg*4] = A1;
        if(cg == 0){ part[b0+64] = d0; part[b1+64] = d1; }
        if(cg < 3){ part[b0+65+cg] = c0a; part[b1+65+cg] = c1a; }
    }
}

__device__ __forceinline__ void normalize_phase(
    float* dyn, const float* __restrict__ part,
    float* __restrict__ prT, float* __restrict__ cp)
{
    float* comb = dyn;   // 8*68
    int lane = threadIdx.x & 31, wid = threadIdx.x >> 5;
    int b = blockIdx.x;
    int v = b / NP, p = b - v*NP;

    float a0=0.f, a1=0.f, den=0.f, ca=0.f;
    #pragma unroll
    for(int k=0;k<2;k++){
        int ch = wid + 8*k;
        size_t bb = ((size_t)(ch*NB + v)*NP + p)*68;
        a0  += part[bb+lane];
        a1  += part[bb+32+lane];
        den += part[bb+64];
        if(lane<3) ca += part[bb+65+lane];
    }
    comb[wid*68+lane]    = a0;
    comb[wid*68+32+lane] = a1;
    if(lane==0) comb[wid*68+64] = den;
    if(lane<3)  comb[wid*68+65+lane] = ca;
    __syncthreads();
    if(wid==0){
        float s0=0.f, s1=0.f, dd=0.f, cc2=0.f;
        #pragma unroll
        for(int k=0;k<8;k++){
            s0 += comb[k*68+lane];
            s1 += comb[k*68+32+lane];
            dd += comb[k*68+64];
            if(lane<3) cc2 += comb[k*68+65+lane];
        }
        float d = dd + 1e-8f;
        float q0 = s0/d, q1 = s1/d;
        float ss = warpSum(q0*q0 + q1*q1);
        float inv = 1.f / fmaxf(sqrtf(ss), 1e-8f);
        prT[(size_t)v*CC*PS + lane*PS + p]      = q0*inv;
        prT[(size_t)v*CC*PS + (lane+32)*PS + p] = q1*inv;
        if(lane<3) cp[(v*NP+p)*3 + lane] = cc2/d;
    }
    __syncthreads();
}

// loss reuses spT/scp* staged by the immediately-preceding assign phase
__device__ __forceinline__ void loss_phase(
    float* dyn, const float* __restrict__ jt,
    const float* __restrict__ se0, const float* __restrict__ sc0,
    const float* __restrict__ se1, const float* __restrict__ sc1,
    const float* __restrict__ tg)
{
    float* spT  = dyn;               // staged
    float* scpx = spT + 64*PS;       // staged
    float* scpy = scpx + 160;
    float* scpz = scpy + 160;
    float* taw  = scpz + 160;        // 12
    float* tah  = taw + 12;          // 12
    float* tad  = tah + 12;          // 16
    __shared__ float bacc[2];

    int tid = threadIdx.x, lane = tid&31, wid = tid>>5;
    int v  = blockIdx.x / (NT/16);
    int m0 = (blockIdx.x - v*(NT/16))*16;

    {
        float tzj = (jt[v*3+0]-0.5f)*2.f*(2.f/32.f);
        float tyj = (jt[v*3+1]-0.5f)*2.f*(8.f/96.f);
        float txj = (jt[v*3+2]-0.5f)*2.f*(8.f/96.f);
        if(tid < 16){
            float gz = ((float)tid + 0.5f)*2.f/16.f - 1.f + tzj;
            tad[tid] = unnorm_reflect(gz, (float)ID);
        }
        if(tid >= 32 && tid < 44){
            int i = tid - 32;
            float gy = ((float)i + 0.5f)*2.f/12.f - 1.f + tyj;
            tah[i] = unnorm_reflect(gy, (float)IH);
        }
        if(tid >= 64 && tid < 76){
            int i = tid - 64;
            float gx = ((float)i + 0.5f)*2.f/12.f - 1.f + txj;
            taw[i] = unnorm_reflect(gx, (float)IW);
        }
    }

    for(int sidx=0; sidx<2; sidx++){
        const float* se  = sidx ? se1 : se0;
        const float* scc = sidx ? sc1 : sc0;
        if(tid < 2) bacc[tid] = 0.f;
        __syncthreads();

        size_t gmb = (size_t)v*NT + m0 + wid*2;
        float r[2][2], s0[2], s1[2], s2[2];
        #pragma unroll
        for(int q=0;q<2;q++){
            r[0][q] = se[(gmb+q)*64 + lane];
            r[1][q] = se[(gmb+q)*64 + 32 + lane];
            s0[q] = scc[(gmb+q)*3+0]; s1[q] = scc[(gmb+q)*3+1]; s2[q] = scc[(gmb+q)*3+2];
        }

        float best[2]; int bi[2];
        #pragma unroll
        for(int q=0;q<2;q++){
            float mh = 1e30f; int ih = 0;
            #pragma unroll
            for(int i=0;i<12;i++){
                float d = s0[q]-tah[i]; float t = d*d;
                if(t < mh){ mh = t; ih = i; }
            }
            float mw = 1e30f; int iw2 = 0;
            #pragma unroll
            for(int i=0;i<12;i++){
                float d = s1[q]-taw[i]; float t = d*d;
                if(t < mw){ mw = t; iw2 = i; }
            }
            float md = 1e30f; int id2 = 0;
            #pragma unroll
            for(int i=0;i<16;i++){
                float d = (s2[q]-tad[i])*2.f; float t = d*d;
                if(t < md){ md = t; id2 = i; }
            }
            best[q] = mh + (mw + md);
            bi[q]   = (id2*12 + ih)*12 + iw2;
        }

        float acc[2][5];
        dot2(spT, lane, r, acc);

        bool v4 = lane < 16;
        #pragma unroll
        for(int q=0;q<2;q++){
            float lg[5], mx = -1e30f;
            #pragma unroll
            for(int j=0;j<5;j++){
                lg[j] = acc[q][j]*(1.f/0.03f);
                if(j<4 || v4) mx = fmaxf(mx, lg[j]);
            }
            mx = warpMax(mx);
            float sum = 0.f;
            #pragma unroll
            for(int j=0;j<5;j++) sum += (j<4||v4) ? expf(lg[j]-mx) : 0.f;
            sum = warpSum(sum);
            float lse = mx + logf(sum);

            const float* tgrow = tg + ((size_t)v*NT + bi[q])*NP;
            float ts = 0.f, ctr = 0.f;
            #pragma unroll
            for(int j=0;j<5;j++){
                if(j==4 && !v4) continue;
                int p = lane + 32*j;
                float dx = s0[q]-scpx[p];
                float dy = s1[q]-scpy[p];
                float dz = (s2[q]-scpz[p])*2.f;
                float pos = (expf(-(dx*dx+dy*dy+dz*dz)*INV2SIG2) >= 0.5f) ? 1.f : 0.f;
                float t = tgrow[p]*pos;
                ts  += t;
                ctr += t*(lg[j]-lse);
            }
            ts  = warpSum(ts);
            ctr = warpSum(ctr);
            if(lane==0 && sqrtf(best[q]) <= 3.0f){
                atomicAdd(&bacc[0], -ctr/(ts + 1e-8f));
                atomicAdd(&bacc[1], 1.f);
            }
        }
        __syncthreads();
        if(tid==0){
            atomicAdd(&g_acc[sidx*2+0], bacc[0]);
            atomicAdd(&g_acc[sidx*2+1], bacc[1]);
        }
        __syncthreads();
    }
}

__global__ void __launch_bounds__(TPB, 2)
fused_em_kernel(float* __restrict__ out, const float* __restrict__ jt)
{
    extern __shared__ float dyn[];
    __shared__ unsigned s_base;

    if(threadIdx.x == 0) s_base = *((volatile unsigned*)&g_flags[blockIdx.x]);
    if(blockIdx.x == 0 && threadIdx.x < 4) g_acc[threadIdx.x] = 0.f;
    __syncthreads();
    unsigned base = s_base;
    unsigned k = 0;

    for(int it=0; it<3; it++){
        assign_phase(dyn, g_tembn, g_ct, g_protosT, g_cp, g_w, 1);
        grid_barrier(base + ++k);
        update_phase(dyn, g_w, g_temb, g_ct, g_part);
        grid_barrier(base + ++k);
        normalize_phase(dyn, g_part, g_protosT, g_cp);
        grid_barrier(base + ++k);
    }
    assign_phase(dyn, g_tembn, g_ct, g_protosT, g_cp, g_tgt, 0);
    grid_barrier(base + ++k);
    loss_phase(dyn, jt, g_s0e, g_s0c, g_s1e, g_s1c, g_tgt);
    grid_barrier(base + ++k);

    if(blockIdx.x == 0 && threadIdx.x == 0){
        out[0] = 0.5f*( g_acc[0]/(g_acc[1] + 1e-8f) + g_acc[2]/(g_acc[3] + 1e-8f) );
    }
}

// ---------------- host launch ----------------
extern "C" void kernel_launch(void* const* d_in, const int* in_sizes, int n_in,
                              void* d_out, int out_size)
{
    const float* e0  = (const float*)d_in[0];
    const float* e1  = (const float*)d_in[1];
    const float* et  = (const float*)d_in[2];
    const float* jp  = (const float*)d_in[7];
    const float* j0  = (const float*)d_in[8];
    const float* j1  = (const float*)d_in[9];
    const float* jt  = (const float*)d_in[10];

    float *protosT,*cp,*temb,*tembn,*ct,*s0e,*s0c,*s1e,*s1c;
    cudaGetSymbolAddress((void**)&protosT, g_protosT);
    cudaGetSymbolAddress((void**)&cp,     g_cp);
    cudaGetSymbolAddress((void**)&temb,   g_temb);
    cudaGetSymbolAddress((void**)&tembn,  g_tembn);
    cudaGetSymbolAddress((void**)&ct,     g_ct);
    cudaGetSymbolAddress((void**)&s0e,    g_s0e);
    cudaGetSymbolAddress((void**)&s0c,    g_s0c);
    cudaGetSymbolAddress((void**)&s1e,    g_s1e);
    cudaGetSymbolAddress((void**)&s1c,    g_s1c);

    size_t fsm = (size_t)(NPER*16 + NPER*64 + NPER*3)*sizeof(float);
    size_t alt = (size_t)(64*PS + 3*160 + 40)*sizeof(float);
    if(alt > fsm) fsm = alt;
    cudaFuncSetAttribute(fused_em_kernel, cudaFuncAttributeMaxDynamicSharedMemorySize, (int)fsm);

    SampleArgs a;
    a.emb[0]=et;  a.emb[1]=e0;  a.emb[2]=e1;
    a.jit[0]=jt;  a.jit[1]=j0;  a.jit[2]=j1;
    a.outn[0]=tembn; a.outn[1]=s0e; a.outn[2]=s1e;
    a.outraw[0]=temb; a.outraw[1]=nullptr; a.outraw[2]=nullptr;
    a.outc[0]=ct; a.outc[1]=s0c; a.outc[2]=s1c;
    a.pemb=et; a.pjit=jp; a.poutT=protosT; a.pcoord=cp;
    sample_all_kernel<<<dim3(288, 4), 256>>>(a);

    fused_em_kernel<<<NBLK, TPB, fsm>>>((float*)d_out, jt);
}